// round 6
// baseline (speedup 1.0000x reference)
#include <cuda_runtime.h>
#include <cuda_fp16.h>

#define NN 100000
#define EE 1600000
#define CC 40
#define NBLK 98          // ceil(NN/1024)
#define LN_EPS 1e-5f

// ---------------- device scratch ----------------
__device__ int    g_cnt[NN];         // histogram, then scatter cursor
__device__ int    g_rptr[NN + 1];    // final CSR row pointers after finalize
__device__ int    g_bsum[NBLK];
__device__ int    g_boff[NBLK];
__device__ int    g_cols[EE];
__device__ float  g_dinv[NN];        // 1/sqrt(deg+1)
__device__ float  g_w[NN];           // 1/(deg+1)
__device__ float  g_sqd[NN];         // sqrt(deg+1)
__device__ float4 g_h32A[NN * 10];   // fp32 state (160 B/row)
__device__ float4 g_h32B[NN * 10];
__device__ uint4  g_h16A[NN * 6];    // fp16 gather copy (96 B/row, 80 B used)
__device__ uint4  g_h16B[NN * 6];

// ---------------- CSR build ----------------
__global__ void hist_kernel(const int4* __restrict__ row4) {
    int i = blockIdx.x * blockDim.x + threadIdx.x;
    if (i < EE / 4) {
        int4 r = row4[i];
        atomicAdd(&g_cnt[r.x], 1);
        atomicAdd(&g_cnt[r.y], 1);
        atomicAdd(&g_cnt[r.z], 1);
        atomicAdd(&g_cnt[r.w], 1);
    }
}

__global__ void scan1_kernel() {
    __shared__ int wsum[32];
    int t = threadIdx.x;
    int i = blockIdx.x * 1024 + t;
    int lane = t & 31, w = t >> 5;
    int v = (i < NN) ? g_cnt[i] : 0;
    int x = v;
    #pragma unroll
    for (int o = 1; o < 32; o <<= 1) {
        int y = __shfl_up_sync(0xffffffffu, x, o);
        if (lane >= o) x += y;
    }
    if (lane == 31) wsum[w] = x;
    __syncthreads();
    if (w == 0) {
        int s = wsum[lane];
        #pragma unroll
        for (int o = 1; o < 32; o <<= 1) {
            int y = __shfl_up_sync(0xffffffffu, s, o);
            if (lane >= o) s += y;
        }
        wsum[lane] = s;
    }
    __syncthreads();
    int incl = x + (w > 0 ? wsum[w - 1] : 0);
    if (i < NN) {
        g_rptr[i] = incl - v;            // chunk-local exclusive
        float df = (float)v + 1.0f;
        g_dinv[i] = rsqrtf(df);
        g_w[i]    = 1.0f / df;
        g_sqd[i]  = sqrtf(df);
    }
    if (t == 1023) g_bsum[blockIdx.x] = incl;
}

__global__ void scan2_kernel() {
    __shared__ int wsum[4];
    int t = threadIdx.x, lane = t & 31, w = t >> 5;
    int v = (t < NBLK) ? g_bsum[t] : 0;
    int x = v;
    #pragma unroll
    for (int o = 1; o < 32; o <<= 1) {
        int y = __shfl_up_sync(0xffffffffu, x, o);
        if (lane >= o) x += y;
    }
    if (lane == 31) wsum[w] = x;
    __syncthreads();
    int pre = 0;
    for (int j = 0; j < w; j++) pre += wsum[j];
    if (t < NBLK) g_boff[t] = pre + x - v;
}

// fold block offsets into rptr; seed scatter cursor (count-up)
__global__ void finalize_kernel() {
    int i = blockIdx.x * blockDim.x + threadIdx.x;
    if (i < NN) {
        int rp = g_rptr[i] + g_boff[i >> 10];
        g_rptr[i] = rp;
        g_cnt[i]  = rp;
    }
    if (i == 0) g_rptr[NN] = EE;
}

// 8 edges per thread for MLP on the L2 atomics
__global__ void scatter_kernel(const int4* __restrict__ row4, const int4* __restrict__ col4) {
    int i = blockIdx.x * blockDim.x + threadIdx.x;
    if (i < EE / 8) {
        int4 r0 = row4[2 * i], r1 = row4[2 * i + 1];
        int4 c0 = col4[2 * i], c1 = col4[2 * i + 1];
        int p;
        p = atomicAdd(&g_cnt[r0.x], 1); g_cols[p] = c0.x;
        p = atomicAdd(&g_cnt[r0.y], 1); g_cols[p] = c0.y;
        p = atomicAdd(&g_cnt[r0.z], 1); g_cols[p] = c0.z;
        p = atomicAdd(&g_cnt[r0.w], 1); g_cols[p] = c0.w;
        p = atomicAdd(&g_cnt[r1.x], 1); g_cols[p] = c1.x;
        p = atomicAdd(&g_cnt[r1.y], 1); g_cols[p] = c1.y;
        p = atomicAdd(&g_cnt[r1.z], 1); g_cols[p] = c1.z;
        p = atomicAdd(&g_cnt[r1.w], 1); g_cols[p] = c1.w;
    }
}

// ---------------- GEMM: s0 = dinv ⊙ (feat @ W^T), dual fp32+fp16 output --------
__global__ void gemm_kernel(const float4* __restrict__ feat4,
                            const float4* __restrict__ W4,
                            float* __restrict__ out32,
                            __half* __restrict__ out16) {
    __shared__ float4 fs[32 * 33];
    __shared__ float4 ws[40 * 32];
    int t = threadIdx.x;
    int n0 = blockIdx.x * 32;
    for (int i = t; i < 32 * 32; i += 256) {
        int r = i >> 5, k4 = i & 31;
        fs[r * 33 + k4] = feat4[(n0 + r) * 32 + k4];
    }
    for (int i = t; i < 40 * 32; i += 256)
        ws[i] = W4[i];
    __syncthreads();

    int n = t & 31;
    int cg = t >> 5;
    const float4* fr = &fs[n * 33];
    const float4* wr = &ws[cg * 5 * 32];
    float acc[5] = {0.f, 0.f, 0.f, 0.f, 0.f};
    #pragma unroll 8
    for (int k4 = 0; k4 < 32; k4++) {
        float4 f = fr[k4];
        #pragma unroll
        for (int j = 0; j < 5; j++) {
            float4 wv = wr[j * 32 + k4];
            acc[j] += f.x * wv.x + f.y * wv.y + f.z * wv.z + f.w * wv.w;
        }
    }
    float dv = g_dinv[n0 + n];
    float*  op = out32 + (n0 + n) * CC + cg * 5;
    __half* hp = out16 + (n0 + n) * 48 + cg * 5;
    #pragma unroll
    for (int j = 0; j < 5; j++) {
        float v = acc[j] * dv;
        op[j] = v;
        hp[j] = __float2half(v);
    }
}

// ---------------- propagation: s' = 0.5 s + 0.5 w (A s + s) -------------------
// warp/row; 6 edge-groups x 5 lanes; gathers from fp16 copy (96 B rows),
// self/residual path from fp32. Dual-writes next state; LAST fuses bias+LN.
template <int LAST>
__global__ void spmm_kernel(const float4* __restrict__ h32in,
                            const uint4*  __restrict__ h16in,
                            float4* __restrict__ h32out,
                            uint4*  __restrict__ h16out,
                            const float4* __restrict__ bias4,
                            const float4* __restrict__ gamma4,
                            const float4* __restrict__ beta4,
                            float4* __restrict__ dout) {
    int lane = threadIdx.x & 31;
    int row  = blockIdx.x * 8 + (threadIdx.x >> 5);
    int sub  = lane / 5;              // 0..5 active edge groups; lanes 30,31 idle
    int fl   = lane - sub * 5;        // 0..4 -> classes 8*fl .. 8*fl+7

    int s = g_rptr[row], e = g_rptr[row + 1];

    float4 accA = make_float4(0.f, 0.f, 0.f, 0.f);
    float4 accB = make_float4(0.f, 0.f, 0.f, 0.f);
    for (int i = s; i < e; i += 6) {
        bool p = (lane < 30) && (i + sub < e);
        if (p) {
            int c = __ldg(&g_cols[i + sub]);         // 5 lanes share -> 1 wavefront
            uint4 v = __ldcg(&h16in[c * 6 + fl]);
            const __half2* hv = reinterpret_cast<const __half2*>(&v);
            float2 f0 = __half22float2(hv[0]);
            float2 f1 = __half22float2(hv[1]);
            float2 f2 = __half22float2(hv[2]);
            float2 f3 = __half22float2(hv[3]);
            accA.x += f0.x; accA.y += f0.y; accA.z += f1.x; accA.w += f1.y;
            accB.x += f2.x; accB.y += f2.y; accB.z += f3.x; accB.w += f3.y;
        }
    }
    // Combine 6 edge groups into lanes 0..4 with GUARDED adds.
    // shfl_down from lane>=32 returns the caller's own value (self-double
    // hazard), and unguarded trees pollute intermediate lanes. Guards ensure
    // each consuming lane only adds provably-pure sources:
    //   off=15 (lane<15): 0..4 = g0+g3, 5..9 = g1+g4, 10..14 = g2+g5
    //   off=10 (lane<5):  += pure g2+g5 from lanes 10..14
    //   off=5  (lane<5):  += pure g1+g4 from lanes 5..9
    {
        float t;
        #define COMB1(x, off, lim) \
            t = __shfl_down_sync(0xffffffffu, x, off); if (lane < lim) x += t;
        #define COMB(x) COMB1(x, 15, 15) COMB1(x, 10, 5) COMB1(x, 5, 5)
        COMB(accA.x) COMB(accA.y) COMB(accA.z) COMB(accA.w)
        COMB(accB.x) COMB(accB.y) COMB(accB.z) COMB(accB.w)
        #undef COMB
        #undef COMB1
    }

    float p1 = 0.f, p2 = 0.f;
    float4 rA, rB;
    if (lane < 5) {
        float4 sA = h32in[row * 10 + 2 * fl];
        float4 sB = h32in[row * 10 + 2 * fl + 1];
        float wv = g_w[row];
        rA.x = 0.5f * sA.x + 0.5f * wv * (accA.x + sA.x);
        rA.y = 0.5f * sA.y + 0.5f * wv * (accA.y + sA.y);
        rA.z = 0.5f * sA.z + 0.5f * wv * (accA.z + sA.z);
        rA.w = 0.5f * sA.w + 0.5f * wv * (accA.w + sA.w);
        rB.x = 0.5f * sB.x + 0.5f * wv * (accB.x + sB.x);
        rB.y = 0.5f * sB.y + 0.5f * wv * (accB.y + sB.y);
        rB.z = 0.5f * sB.z + 0.5f * wv * (accB.z + sB.z);
        rB.w = 0.5f * sB.w + 0.5f * wv * (accB.w + sB.w);
        if (!LAST) {
            h32out[row * 10 + 2 * fl]     = rA;
            h32out[row * 10 + 2 * fl + 1] = rB;
            uint4 hv;
            __half2* hp = reinterpret_cast<__half2*>(&hv);
            hp[0] = __floats2half2_rn(rA.x, rA.y);
            hp[1] = __floats2half2_rn(rA.z, rA.w);
            hp[2] = __floats2half2_rn(rB.x, rB.y);
            hp[3] = __floats2half2_rn(rB.z, rB.w);
            h16out[row * 6 + fl] = hv;
        } else {
            float q = g_sqd[row];                 // unscale: h = s * sqrt(deg+1)
            float4 bA = bias4[2 * fl], bB = bias4[2 * fl + 1];
            rA.x = rA.x * q + bA.x;  rA.y = rA.y * q + bA.y;
            rA.z = rA.z * q + bA.z;  rA.w = rA.w * q + bA.w;
            rB.x = rB.x * q + bB.x;  rB.y = rB.y * q + bB.y;
            rB.z = rB.z * q + bB.z;  rB.w = rB.w * q + bB.w;
            p1 = rA.x + rA.y + rA.z + rA.w + rB.x + rB.y + rB.z + rB.w;
            p2 = rA.x * rA.x + rA.y * rA.y + rA.z * rA.z + rA.w * rA.w
               + rB.x * rB.x + rB.y * rB.y + rB.z * rB.z + rB.w * rB.w;
        }
    }
    if (LAST) {
        #pragma unroll
        for (int o = 16; o; o >>= 1) {
            p1 += __shfl_xor_sync(0xffffffffu, p1, o);
            p2 += __shfl_xor_sync(0xffffffffu, p2, o);
        }
        if (lane < 5) {
            float mu   = p1 * (1.0f / CC);
            float rstd = rsqrtf(p2 * (1.0f / CC) - mu * mu + LN_EPS);
            float4 gA = gamma4[2 * fl], gB = gamma4[2 * fl + 1];
            float4 eA = beta4[2 * fl],  eB = beta4[2 * fl + 1];
            float4 oA, oB;
            oA.x = (rA.x - mu) * rstd * gA.x + eA.x;
            oA.y = (rA.y - mu) * rstd * gA.y + eA.y;
            oA.z = (rA.z - mu) * rstd * gA.z + eA.z;
            oA.w = (rA.w - mu) * rstd * gA.w + eA.w;
            oB.x = (rB.x - mu) * rstd * gB.x + eB.x;
            oB.y = (rB.y - mu) * rstd * gB.y + eB.y;
            oB.z = (rB.z - mu) * rstd * gB.z + eB.z;
            oB.w = (rB.w - mu) * rstd * gB.w + eB.w;
            dout[row * 10 + 2 * fl]     = oA;
            dout[row * 10 + 2 * fl + 1] = oB;
        }
    }
}

// ---------------- launch ----------------
extern "C" void kernel_launch(void* const* d_in, const int* in_sizes, int n_in,
                              void* d_out, int out_size) {
    const float* feat  = (const float*)d_in[0];
    const int*   row   = (const int*)d_in[1];
    const int*   col   = (const int*)d_in[2];
    const float* W     = (const float*)d_in[3];
    const float* bias  = (const float*)d_in[4];
    const float* gamma = (const float*)d_in[5];
    const float* beta  = (const float*)d_in[6];

    void *pCnt, *pA32, *pB32, *pA16, *pB16;
    cudaGetSymbolAddress(&pCnt, g_cnt);
    cudaGetSymbolAddress(&pA32, g_h32A);
    cudaGetSymbolAddress(&pB32, g_h32B);
    cudaGetSymbolAddress(&pA16, g_h16A);
    cudaGetSymbolAddress(&pB16, g_h16B);
    float4* A32 = (float4*)pA32;  float4* B32 = (float4*)pB32;
    uint4*  A16 = (uint4*)pA16;   uint4*  B16 = (uint4*)pB16;

    cudaMemsetAsync(pCnt, 0, NN * sizeof(int));
    hist_kernel<<<(EE / 4 + 255) / 256, 256>>>((const int4*)row);
    scan1_kernel<<<NBLK, 1024>>>();
    scan2_kernel<<<1, 128>>>();
    finalize_kernel<<<(NN + 255) / 256, 256>>>();
    scatter_kernel<<<(EE / 8 + 255) / 256, 256>>>((const int4*)row, (const int4*)col);

    gemm_kernel<<<NN / 32, 256>>>((const float4*)feat, (const float4*)W,
                                  (float*)pA32, (__half*)pA16);

    int sblocks = NN / 8;
    spmm_kernel<0><<<sblocks, 256>>>(A32, A16, B32, B16, nullptr, nullptr, nullptr, nullptr);
    spmm_kernel<0><<<sblocks, 256>>>(B32, B16, A32, A16, nullptr, nullptr, nullptr, nullptr);
    spmm_kernel<0><<<sblocks, 256>>>(A32, A16, B32, B16, nullptr, nullptr, nullptr, nullptr);
    spmm_kernel<1><<<sblocks, 256>>>(B32, B16, nullptr, nullptr,
                                     (const float4*)bias, (const float4*)gamma,
                                     (const float4*)beta, (float4*)d_out);
}

// round 7
// speedup vs baseline: 1.0694x; 1.0694x over previous
#include <cuda_runtime.h>
#include <cuda_fp16.h>

#define NN 100000
#define EE 1600000
#define CC 40
#define NBLK 98          // ceil(NN/1024)
#define LN_EPS 1e-5f

// ---------------- device scratch ----------------
// g_cnt: zero at process start; hist builds degree; countdown scatter restores
// it to exactly 0 -> every graph replay sees identical state (deterministic).
__device__ int    g_cnt[NN];
__device__ int    g_rptr[NN + 1];
__device__ volatile int g_flag[NBLK];   // lookback: 0=none,1=aggregate,2=inclusive (reset by gemm)
__device__ volatile int g_aggr[NBLK];
__device__ volatile int g_incl[NBLK];
__device__ int    g_cols[EE];
__device__ float  g_dinv[NN];        // 1/sqrt(deg+1)
__device__ float  g_w[NN];           // 1/(deg+1)
__device__ float  g_sqd[NN];         // sqrt(deg+1)
__device__ float4 g_h32A[NN * 10];   // fp32 state (160 B/row)
__device__ float4 g_h32B[NN * 10];
__device__ uint4  g_h16A[NN * 6];    // fp16 gather copy (96 B/row, 80 B used)
__device__ uint4  g_h16B[NN * 6];

// ---------------- histogram (8 edges/thread for atomic MLP) ----------------
__global__ void hist_kernel(const int4* __restrict__ row4) {
    int i = blockIdx.x * blockDim.x + threadIdx.x;
    if (i < EE / 8) {
        int4 a = row4[2 * i], b = row4[2 * i + 1];
        atomicAdd(&g_cnt[a.x], 1);
        atomicAdd(&g_cnt[a.y], 1);
        atomicAdd(&g_cnt[a.z], 1);
        atomicAdd(&g_cnt[a.w], 1);
        atomicAdd(&g_cnt[b.x], 1);
        atomicAdd(&g_cnt[b.y], 1);
        atomicAdd(&g_cnt[b.z], 1);
        atomicAdd(&g_cnt[b.w], 1);
    }
}

// ---------------- single-kernel decoupled-lookback scan --------------------
// 98 blocks x 1024 threads (all resident in wave 1 on 148 SMs; blocks only
// wait on lower-indexed blocks -> no deadlock). Produces FINAL rptr + dinv/w/sqd.
__global__ void scan_kernel() {
    __shared__ int wsum[32];
    __shared__ int chunk_prefix;
    int t = threadIdx.x, b = blockIdx.x;
    int i = b * 1024 + t;
    int lane = t & 31, w = t >> 5;
    int v = (i < NN) ? g_cnt[i] : 0;
    int x = v;
    #pragma unroll
    for (int o = 1; o < 32; o <<= 1) {
        int y = __shfl_up_sync(0xffffffffu, x, o);
        if (lane >= o) x += y;
    }
    if (lane == 31) wsum[w] = x;
    __syncthreads();
    if (w == 0) {
        int s = wsum[lane];
        #pragma unroll
        for (int o = 1; o < 32; o <<= 1) {
            int y = __shfl_up_sync(0xffffffffu, s, o);
            if (lane >= o) s += y;
        }
        wsum[lane] = s;
    }
    __syncthreads();
    int incl = x + (w > 0 ? wsum[w - 1] : 0);   // inclusive within chunk

    if (t == 1023) {                            // chunk total lives here
        g_aggr[b] = incl;
        __threadfence();
        g_flag[b] = 1;
        int sum = 0;
        for (int p = b - 1; p >= 0; ) {
            int f;
            while ((f = g_flag[p]) == 0) { }
            if (f == 2) { sum += g_incl[p]; break; }
            sum += g_aggr[p];
            --p;
        }
        g_incl[b] = sum + incl;
        __threadfence();
        g_flag[b] = 2;
        chunk_prefix = sum;
        if (b == NBLK - 1) g_rptr[NN] = EE;
    }
    __syncthreads();
    int pre = chunk_prefix;
    if (i < NN) {
        g_rptr[i] = pre + incl - v;             // FINAL exclusive prefix
        float df = (float)v + 1.0f;
        g_dinv[i] = rsqrtf(df);
        g_w[i]    = 1.0f / df;
        g_sqd[i]  = sqrtf(df);
    }
}

// ---------------- countdown scatter (restores g_cnt to 0) ------------------
__global__ void scatter_kernel(const int4* __restrict__ row4, const int4* __restrict__ col4) {
    int i = blockIdx.x * blockDim.x + threadIdx.x;
    if (i < EE / 8) {
        int4 r0 = row4[2 * i], r1 = row4[2 * i + 1];
        int4 c0 = col4[2 * i], c1 = col4[2 * i + 1];
        int p;
        p = g_rptr[r0.x] + atomicAdd(&g_cnt[r0.x], -1) - 1; g_cols[p] = c0.x;
        p = g_rptr[r0.y] + atomicAdd(&g_cnt[r0.y], -1) - 1; g_cols[p] = c0.y;
        p = g_rptr[r0.z] + atomicAdd(&g_cnt[r0.z], -1) - 1; g_cols[p] = c0.z;
        p = g_rptr[r0.w] + atomicAdd(&g_cnt[r0.w], -1) - 1; g_cols[p] = c0.w;
        p = g_rptr[r1.x] + atomicAdd(&g_cnt[r1.x], -1) - 1; g_cols[p] = c1.x;
        p = g_rptr[r1.y] + atomicAdd(&g_cnt[r1.y], -1) - 1; g_cols[p] = c1.y;
        p = g_rptr[r1.z] + atomicAdd(&g_cnt[r1.z], -1) - 1; g_cols[p] = c1.z;
        p = g_rptr[r1.w] + atomicAdd(&g_cnt[r1.w], -1) - 1; g_cols[p] = c1.w;
    }
}

// ---------------- GEMM: s0 = dinv ⊙ (feat @ W^T), smem-staged coalesced out --
__global__ void gemm_kernel(const float4* __restrict__ feat4,
                            const float4* __restrict__ W4,
                            float4* __restrict__ out32,     // base of fp32 buffer
                            uint4*  __restrict__ out16) {   // base of fp16 buffer
    __shared__ float4 fs[32 * 33];
    __shared__ float4 ws[40 * 32];
    __shared__ float  os[32 * 40];      // fp32 staging (contiguous rows)
    __shared__ __half hs[32 * 40];      // fp16 staging (80 B rows)
    int t = threadIdx.x;
    int n0 = blockIdx.x * 32;

    // reset lookback flags for the next graph replay (stream-ordered after scan)
    if (blockIdx.x == 0 && t < NBLK) g_flag[t] = 0;

    for (int i = t; i < 32 * 32; i += 256) {
        int r = i >> 5, k4 = i & 31;
        fs[r * 33 + k4] = feat4[(n0 + r) * 32 + k4];
    }
    for (int i = t; i < 40 * 32; i += 256)
        ws[i] = W4[i];
    __syncthreads();

    int n = t & 31;
    int cg = t >> 5;                     // 5 classes per thread
    const float4* fr = &fs[n * 33];
    const float4* wr = &ws[cg * 5 * 32];
    float acc[5] = {0.f, 0.f, 0.f, 0.f, 0.f};
    #pragma unroll 8
    for (int k4 = 0; k4 < 32; k4++) {
        float4 f = fr[k4];
        #pragma unroll
        for (int j = 0; j < 5; j++) {
            float4 wv = wr[j * 32 + k4];
            acc[j] += f.x * wv.x + f.y * wv.y + f.z * wv.z + f.w * wv.w;
        }
    }
    float dv = g_dinv[n0 + n];
    #pragma unroll
    for (int j = 0; j < 5; j++) {
        float v = acc[j] * dv;
        os[n * 40 + cg * 5 + j] = v;
        hs[n * 40 + cg * 5 + j] = __float2half(v);
    }
    __syncthreads();

    // coalesced output: fp32 rows are globally contiguous (40 floats/node)
    const float4* os4 = (const float4*)os;
    for (int i = t; i < 320; i += 256)
        out32[blockIdx.x * 320 + i] = os4[i];
    // fp16: 5 uint4 per node into 6-uint4-stride rows
    const uint4* hs4 = (const uint4*)hs;
    for (int i = t; i < 160; i += 256) {
        int nn = i / 5, fl = i % 5;
        out16[(n0 + nn) * 6 + fl] = hs4[nn * 5 + fl];
    }
}

// ---------------- propagation: s' = 0.5 s + 0.5 w (A s + s) -------------------
template <int LAST>
__global__ void spmm_kernel(const float4* __restrict__ h32in,
                            const uint4*  __restrict__ h16in,
                            float4* __restrict__ h32out,
                            uint4*  __restrict__ h16out,
                            const float4* __restrict__ bias4,
                            const float4* __restrict__ gamma4,
                            const float4* __restrict__ beta4,
                            float4* __restrict__ dout) {
    int lane = threadIdx.x & 31;
    int row  = blockIdx.x * 8 + (threadIdx.x >> 5);
    int sub  = lane / 5;              // 0..5 active edge groups; lanes 30,31 idle
    int fl   = lane - sub * 5;        // 0..4 -> uint4 slot in row

    int s = g_rptr[row], e = g_rptr[row + 1];

    float4 accA = make_float4(0.f, 0.f, 0.f, 0.f);
    float4 accB = make_float4(0.f, 0.f, 0.f, 0.f);
    #pragma unroll 2
    for (int i = s; i < e; i += 6) {
        bool p = (lane < 30) && (i + sub < e);
        if (p) {
            int c = __ldg(&g_cols[i + sub]);
            uint4 v = __ldcg(&h16in[c * 6 + fl]);
            const __half2* hv = reinterpret_cast<const __half2*>(&v);
            float2 f0 = __half22float2(hv[0]);
            float2 f1 = __half22float2(hv[1]);
            float2 f2 = __half22float2(hv[2]);
            float2 f3 = __half22float2(hv[3]);
            accA.x += f0.x; accA.y += f0.y; accA.z += f1.x; accA.w += f1.y;
            accB.x += f2.x; accB.y += f2.y; accB.z += f3.x; accB.w += f3.y;
        }
    }
    // guarded 6-group combine (see R4/R6 post-mortems: shfl self-return + lane
    // pollution hazards). off=15 (lane<15), off=10 (lane<5), off=5 (lane<5).
    {
        float t;
        #define COMB1(x, off, lim) \
            t = __shfl_down_sync(0xffffffffu, x, off); if (lane < lim) x += t;
        #define COMB(x) COMB1(x, 15, 15) COMB1(x, 10, 5) COMB1(x, 5, 5)
        COMB(accA.x) COMB(accA.y) COMB(accA.z) COMB(accA.w)
        COMB(accB.x) COMB(accB.y) COMB(accB.z) COMB(accB.w)
        #undef COMB
        #undef COMB1
    }

    float p1 = 0.f, p2 = 0.f;
    float4 rA, rB;
    if (lane < 5) {
        float4 sA = h32in[row * 10 + 2 * fl];
        float4 sB = h32in[row * 10 + 2 * fl + 1];
        float wv = g_w[row];
        rA.x = 0.5f * sA.x + 0.5f * wv * (accA.x + sA.x);
        rA.y = 0.5f * sA.y + 0.5f * wv * (accA.y + sA.y);
        rA.z = 0.5f * sA.z + 0.5f * wv * (accA.z + sA.z);
        rA.w = 0.5f * sA.w + 0.5f * wv * (accA.w + sA.w);
        rB.x = 0.5f * sB.x + 0.5f * wv * (accB.x + sB.x);
        rB.y = 0.5f * sB.y + 0.5f * wv * (accB.y + sB.y);
        rB.z = 0.5f * sB.z + 0.5f * wv * (accB.z + sB.z);
        rB.w = 0.5f * sB.w + 0.5f * wv * (accB.w + sB.w);
        if (!LAST) {
            h32out[row * 10 + 2 * fl]     = rA;
            h32out[row * 10 + 2 * fl + 1] = rB;
            uint4 hv;
            __half2* hp = reinterpret_cast<__half2*>(&hv);
            hp[0] = __floats2half2_rn(rA.x, rA.y);
            hp[1] = __floats2half2_rn(rA.z, rA.w);
            hp[2] = __floats2half2_rn(rB.x, rB.y);
            hp[3] = __floats2half2_rn(rB.z, rB.w);
            h16out[row * 6 + fl] = hv;
        } else {
            float q = g_sqd[row];                 // unscale: h = s * sqrt(deg+1)
            float4 bA = bias4[2 * fl], bB = bias4[2 * fl + 1];
            rA.x = rA.x * q + bA.x;  rA.y = rA.y * q + bA.y;
            rA.z = rA.z * q + bA.z;  rA.w = rA.w * q + bA.w;
            rB.x = rB.x * q + bB.x;  rB.y = rB.y * q + bB.y;
            rB.z = rB.z * q + bB.z;  rB.w = rB.w * q + bB.w;
            p1 = rA.x + rA.y + rA.z + rA.w + rB.x + rB.y + rB.z + rB.w;
            p2 = rA.x * rA.x + rA.y * rA.y + rA.z * rA.z + rA.w * rA.w
               + rB.x * rB.x + rB.y * rB.y + rB.z * rB.z + rB.w * rB.w;
        }
    }
    if (LAST) {
        #pragma unroll
        for (int o = 16; o; o >>= 1) {
            p1 += __shfl_xor_sync(0xffffffffu, p1, o);
            p2 += __shfl_xor_sync(0xffffffffu, p2, o);
        }
        if (lane < 5) {
            float mu   = p1 * (1.0f / CC);
            float rstd = rsqrtf(p2 * (1.0f / CC) - mu * mu + LN_EPS);
            float4 gA = gamma4[2 * fl], gB = gamma4[2 * fl + 1];
            float4 eA = beta4[2 * fl],  eB = beta4[2 * fl + 1];
            float4 oA, oB;
            oA.x = (rA.x - mu) * rstd * gA.x + eA.x;
            oA.y = (rA.y - mu) * rstd * gA.y + eA.y;
            oA.z = (rA.z - mu) * rstd * gA.z + eA.z;
            oA.w = (rA.w - mu) * rstd * gA.w + eA.w;
            oB.x = (rB.x - mu) * rstd * gB.x + eB.x;
            oB.y = (rB.y - mu) * rstd * gB.y + eB.y;
            oB.z = (rB.z - mu) * rstd * gB.z + eB.z;
            oB.w = (rB.w - mu) * rstd * gB.w + eB.w;
            dout[row * 10 + 2 * fl]     = oA;
            dout[row * 10 + 2 * fl + 1] = oB;
        }
    }
}

// ---------------- launch ----------------
extern "C" void kernel_launch(void* const* d_in, const int* in_sizes, int n_in,
                              void* d_out, int out_size) {
    const float* feat  = (const float*)d_in[0];
    const int*   row   = (const int*)d_in[1];
    const int*   col   = (const int*)d_in[2];
    const float* W     = (const float*)d_in[3];
    const float* bias  = (const float*)d_in[4];
    const float* gamma = (const float*)d_in[5];
    const float* beta  = (const float*)d_in[6];

    void *pA32, *pB32, *pA16, *pB16;
    cudaGetSymbolAddress(&pA32, g_h32A);
    cudaGetSymbolAddress(&pB32, g_h32B);
    cudaGetSymbolAddress(&pA16, g_h16A);
    cudaGetSymbolAddress(&pB16, g_h16B);
    float4* A32 = (float4*)pA32;  float4* B32 = (float4*)pB32;
    uint4*  A16 = (uint4*)pA16;   uint4*  B16 = (uint4*)pB16;

    // launch #1..#4, then spmm1 lands at position 5 (the ncu -s 5 -c 1 window)
    hist_kernel<<<(EE / 8 + 255) / 256, 256>>>((const int4*)row);
    scan_kernel<<<NBLK, 1024>>>();
    scatter_kernel<<<(EE / 8 + 255) / 256, 256>>>((const int4*)row, (const int4*)col);
    gemm_kernel<<<NN / 32, 256>>>((const float4*)feat, (const float4*)W, A32, A16);

    int sblocks = NN / 8;
    spmm_kernel<0><<<sblocks, 256>>>(A32, A16, B32, B16, nullptr, nullptr, nullptr, nullptr);
    spmm_kernel<0><<<sblocks, 256>>>(B32, B16, A32, A16, nullptr, nullptr, nullptr, nullptr);
    spmm_kernel<0><<<sblocks, 256>>>(A32, A16, B32, B16, nullptr, nullptr, nullptr, nullptr);
    spmm_kernel<1><<<sblocks, 256>>>(B32, B16, nullptr, nullptr,
                                     (const float4*)bias, (const float4*)gamma,
                                     (const float4*)beta, (float4*)d_out);
}